// round 1
// baseline (speedup 1.0000x reference)
#include <cuda_runtime.h>
#include <math.h>

#define Bb 4
#define Mm 2048
#define Cc 512
#define Hh 8
#define DQKd 16
#define DVd 64

// Scratch for projections (no cudaMalloc allowed)
__device__ float g_Q[Bb * Hh * Mm * DQKd];   // (bh, m, 16)
__device__ float g_K[Bb * Hh * Mm * DQKd];   // (bh, m, 16)
__device__ float g_V[Bb * Hh * Mm * DVd];    // (bh, m, 64)

// ---------------------------------------------------------------------------
// Kernel 1: fused QKV projection.  out(8192 x 768) = x(8192 x 512) @ [Wq|Wk|Wv]
// Tiles: BM=64, BN=64, BK=16; 256 threads; 4x4 register tile per thread.
// ---------------------------------------------------------------------------
__global__ __launch_bounds__(256) void proj_kernel(
    const float* __restrict__ x,
    const float* __restrict__ Wq, const float* __restrict__ bq,
    const float* __restrict__ Wk, const float* __restrict__ bk,
    const float* __restrict__ Wv, const float* __restrict__ bv)
{
    const int BM = 64, BN = 64, BK = 16;
    __shared__ float As[BK][BM + 4];   // transposed x tile
    __shared__ float Bs[BK][BN + 4];

    const int row0 = blockIdx.x * BM;
    const int col0 = blockIdx.y * BN;
    const int tid = threadIdx.x;
    const int tx = tid & 15;
    const int ty = tid >> 4;

    const float* W; const float* bias; int ldw; int jofs;
    if (col0 < 128)      { W = Wq; bias = bq; ldw = 128; jofs = col0;       }
    else if (col0 < 256) { W = Wk; bias = bk; ldw = 128; jofs = col0 - 128; }
    else                 { W = Wv; bias = bv; ldw = 512; jofs = col0 - 256; }

    float acc[4][4] = {};

    const int lr  = tid >> 2;   // 0..63 row for A loads
    const int lkq = tid & 3;    // 0..3  k-quad for A loads
    const int lkk = tid >> 4;   // 0..15 k for B loads
    const int lcq = tid & 15;   // 0..15 col-quad for B loads

    for (int k0 = 0; k0 < Cc; k0 += BK) {
        float4 av = *(const float4*)&x[(size_t)(row0 + lr) * Cc + k0 + lkq * 4];
        As[lkq * 4 + 0][lr] = av.x;
        As[lkq * 4 + 1][lr] = av.y;
        As[lkq * 4 + 2][lr] = av.z;
        As[lkq * 4 + 3][lr] = av.w;
        float4 bv4 = *(const float4*)&W[(size_t)(k0 + lkk) * ldw + jofs + lcq * 4];
        *(float4*)&Bs[lkk][lcq * 4] = bv4;
        __syncthreads();
#pragma unroll
        for (int kk = 0; kk < BK; kk++) {
            float4 a = *(const float4*)&As[kk][ty * 4];
            float4 b = *(const float4*)&Bs[kk][tx * 4];
            float ar[4] = {a.x, a.y, a.z, a.w};
            float br[4] = {b.x, b.y, b.z, b.w};
#pragma unroll
            for (int i = 0; i < 4; i++)
#pragma unroll
                for (int j = 0; j < 4; j++)
                    acc[i][j] = fmaf(ar[i], br[j], acc[i][j]);
        }
        __syncthreads();
    }

    // epilogue: add bias, scatter into head-major Q/K/V scratch
#pragma unroll
    for (int j = 0; j < 4; j++) {
        const int jg = col0 + tx * 4 + j;
        const float bval = bias[jofs + tx * 4 + j];
#pragma unroll
        for (int i = 0; i < 4; i++) {
            const int rg = row0 + ty * 4 + i;
            const int b  = rg >> 11;        // / Mm
            const int m  = rg & (Mm - 1);
            const float v = acc[i][j] + bval;
            if (jg < 128) {
                g_Q[(((size_t)(b * Hh + (jg >> 4)) * Mm) + m) * DQKd + (jg & 15)] = v;
            } else if (jg < 256) {
                const int jj = jg - 128;
                g_K[(((size_t)(b * Hh + (jj >> 4)) * Mm) + m) * DQKd + (jj & 15)] = v;
            } else {
                const int jj = jg - 256;
                g_V[(((size_t)(b * Hh + (jj >> 6)) * Mm) + m) * DVd + (jj & 63)] = v;
            }
        }
    }
}

// ---------------------------------------------------------------------------
// Kernel 2: fused attention. One CTA per (b, h, 64-row q tile). 256 threads.
// Rescale-free streaming: w = mask * exp(relu(q.k * 0.25)); o = (Σ w v)/(Σ w).
// ---------------------------------------------------------------------------
__global__ __launch_bounds__(256) void attn_kernel(
    const int* __restrict__ mask, const float* __restrict__ gamma,
    float* __restrict__ out)
{
    const int BM = 64, BN = 64;
    __shared__ float QT[DQKd][BM + 4];   // transposed Q tile
    __shared__ float KT[DQKd][BN + 4];   // transposed K tile
    __shared__ float Vs[BN][DVd];        // V tile row-major (float4-phase friendly)
    __shared__ float Ws[BM][BN + 4];     // weights row-major
    __shared__ float rowTot[BM];
    __shared__ float wm[BN];

    const int bh = blockIdx.x >> 5;        // 0..31
    const int mt = blockIdx.x & 31;
    const int b  = bh >> 3;
    const int h  = bh & 7;
    const int m0 = mt * BM;
    const int tid = threadIdx.x;
    const int tx = tid & 15;
    const int ty = tid >> 4;

    const float* Qp = g_Q + (size_t)bh * Mm * DQKd;
    const float* Kp = g_K + (size_t)bh * Mm * DQKd;
    const float* Vp = g_V + (size_t)bh * Mm * DVd;

    {   // load Q tile transposed
        const int r = tid >> 2, kq = tid & 3;
        float4 qv = *(const float4*)&Qp[(size_t)(m0 + r) * DQKd + kq * 4];
        QT[kq * 4 + 0][r] = qv.x;
        QT[kq * 4 + 1][r] = qv.y;
        QT[kq * 4 + 2][r] = qv.z;
        QT[kq * 4 + 3][r] = qv.w;
    }
    if (tid < BM) rowTot[tid] = 0.0f;

    float acc[4][4] = {};
    float rsum[4] = {};
    const float scale = 0.25f;   // 1/sqrt(16)

    for (int nt = 0; nt < Mm / BN; nt++) {
        const int n0 = nt * BN;
        __syncthreads();   // previous tile's PV finished (and QT visible, iter 0)
        {   // load K tile transposed
            const int c = tid >> 2, kq = tid & 3;
            float4 kv = *(const float4*)&Kp[(size_t)(n0 + c) * DQKd + kq * 4];
            KT[kq * 4 + 0][c] = kv.x;
            KT[kq * 4 + 1][c] = kv.y;
            KT[kq * 4 + 2][c] = kv.z;
            KT[kq * 4 + 3][c] = kv.w;
        }
#pragma unroll
        for (int l = 0; l < 4; l++) {   // load V tile
            const int idx = tid + l * 256;
            const int c = idx >> 4, dq = idx & 15;
            *(float4*)&Vs[c][dq * 4] =
                *(const float4*)&Vp[(size_t)(n0 + c) * DVd + dq * 4];
        }
        if (tid < BN) wm[tid] = (float)mask[b * Mm + n0 + tid];
        __syncthreads();

        // S = Q K^T (4x4 per thread)
        float s[4][4] = {};
#pragma unroll
        for (int kk = 0; kk < DQKd; kk++) {
            float4 a  = *(const float4*)&QT[kk][ty * 4];
            float4 bb = *(const float4*)&KT[kk][tx * 4];
            float ar[4] = {a.x, a.y, a.z, a.w};
            float br[4] = {bb.x, bb.y, bb.z, bb.w};
#pragma unroll
            for (int i = 0; i < 4; i++)
#pragma unroll
                for (int j = 0; j < 4; j++)
                    s[i][j] = fmaf(ar[i], br[j], s[i][j]);
        }

        // w = mask * exp(relu(s*scale)); stash row-major in smem
#pragma unroll
        for (int i = 0; i < 4; i++) {
            float4 wv;
            float w0 = wm[tx * 4 + 0] * __expf(fmaxf(s[i][0] * scale, 0.0f));
            float w1 = wm[tx * 4 + 1] * __expf(fmaxf(s[i][1] * scale, 0.0f));
            float w2 = wm[tx * 4 + 2] * __expf(fmaxf(s[i][2] * scale, 0.0f));
            float w3 = wm[tx * 4 + 3] * __expf(fmaxf(s[i][3] * scale, 0.0f));
            rsum[i] += (w0 + w1) + (w2 + w3);
            wv.x = w0; wv.y = w1; wv.z = w2; wv.w = w3;
            *(float4*)&Ws[ty * 4 + i][tx * 4] = wv;
        }
        __syncthreads();

        // O += W V   (4x4 per thread; w reads broadcast, V reads float4)
#pragma unroll 8
        for (int c = 0; c < BN; c++) {
            const float w0 = Ws[ty * 4 + 0][c];
            const float w1 = Ws[ty * 4 + 1][c];
            const float w2 = Ws[ty * 4 + 2][c];
            const float w3 = Ws[ty * 4 + 3][c];
            float4 vv = *(const float4*)&Vs[c][tx * 4];
            acc[0][0] = fmaf(w0, vv.x, acc[0][0]);
            acc[0][1] = fmaf(w0, vv.y, acc[0][1]);
            acc[0][2] = fmaf(w0, vv.z, acc[0][2]);
            acc[0][3] = fmaf(w0, vv.w, acc[0][3]);
            acc[1][0] = fmaf(w1, vv.x, acc[1][0]);
            acc[1][1] = fmaf(w1, vv.y, acc[1][1]);
            acc[1][2] = fmaf(w1, vv.z, acc[1][2]);
            acc[1][3] = fmaf(w1, vv.w, acc[1][3]);
            acc[2][0] = fmaf(w2, vv.x, acc[2][0]);
            acc[2][1] = fmaf(w2, vv.y, acc[2][1]);
            acc[2][2] = fmaf(w2, vv.z, acc[2][2]);
            acc[2][3] = fmaf(w2, vv.w, acc[2][3]);
            acc[3][0] = fmaf(w3, vv.x, acc[3][0]);
            acc[3][1] = fmaf(w3, vv.y, acc[3][1]);
            acc[3][2] = fmaf(w3, vv.z, acc[3][2]);
            acc[3][3] = fmaf(w3, vv.w, acc[3][3]);
        }
    }

    // reduce row sums across tx groups
#pragma unroll
    for (int i = 0; i < 4; i++) atomicAdd(&rowTot[ty * 4 + i], rsum[i]);
    __syncthreads();

    const float g = *gamma;
#pragma unroll
    for (int i = 0; i < 4; i++) {
        const int m = m0 + ty * 4 + i;
        const float inv = g / rowTot[ty * 4 + i];
        float4 o4;
        o4.x = acc[i][0] * inv;
        o4.y = acc[i][1] * inv;
        o4.z = acc[i][2] * inv;
        o4.w = acc[i][3] * inv;
        *(float4*)&out[((size_t)b * Mm + m) * Cc + h * DVd + tx * 4] = o4;
    }
}

// ---------------------------------------------------------------------------
extern "C" void kernel_launch(void* const* d_in, const int* in_sizes, int n_in,
                              void* d_out, int out_size)
{
    const float* x     = (const float*)d_in[0];
    const int*   mask  = (const int*)  d_in[1];
    const float* Wq    = (const float*)d_in[2];
    const float* bq    = (const float*)d_in[3];
    const float* Wk    = (const float*)d_in[4];
    const float* bk    = (const float*)d_in[5];
    const float* Wv    = (const float*)d_in[6];
    const float* bv    = (const float*)d_in[7];
    const float* gamma = (const float*)d_in[8];
    float* out = (float*)d_out;

    dim3 pg((Bb * Mm) / 64, (Cc / 4 + Cc / 4 + Cc) / 64);  // (128, 12)
    proj_kernel<<<pg, 256>>>(x, Wq, bq, Wk, bk, Wv, bv);

    dim3 ag(Bb * Hh * (Mm / 64));                          // 1024
    attn_kernel<<<ag, 256>>>(mask, gamma, out);
}